// round 5
// baseline (speedup 1.0000x reference)
#include <cuda_runtime.h>

namespace {

constexpr int D    = 16;
constexpr int KNN  = 16;
constexpr int GS2  = 20;                  // fine grid cells per axis
constexpr int NC2  = GS2 * GS2 * GS2;     // 8000 fine cells
constexpr int SC   = 10;                  // supercells per axis
constexpr int NSC  = SC * SC * SC;        // 1000 supercells
constexpr int QCAP = 320;                 // queries per supercell capacity (mean ~82)
constexpr int MMAX = 20000;
constexpr int NMAX = 81920;
constexpr int RCAP = 768;                 // staged atoms per block (mean ~540)
constexpr int LBN  = 125;                 // static offset list size ([-2..2]^3)
constexpr int KB   = 128;                 // kNN block size

} // namespace

// ---- scratch (no allocs allowed) ----
__device__ int    g_ccnt[NC2];
__device__ int    g_cstart[NC2 + 1];
__device__ int    g_ccur[NC2];
__device__ float4 g_catoms[MMAX];
__device__ int    g_qcnt[NSC];
__device__ int    g_qidx[NSC * QCAP];
__device__ int    g_bbenc[6];
__device__ float  g_org[3], g_h[3], g_hinv[3], g_hmin;
__device__ int    g_offpack[LBN];         // (ox+2) | (oy+2)<<4 | (oz+2)<<8
__device__ float  g_lbmono[LBN];          // suffix-min of physical LB^2
__device__ float  g_ndist[NMAX * KNN];
__device__ int    g_nidx[NMAX * KNN];

namespace {

__device__ __forceinline__ int fenc(float f) {
    int b = __float_as_int(f);
    return (b < 0) ? (b ^ 0x7fffffff) : b;
}
__device__ __forceinline__ float fdec(int b) {
    return __int_as_float((b < 0) ? (b ^ 0x7fffffff) : b);
}

__global__ void k_init() {
    int i = blockIdx.x * blockDim.x + threadIdx.x;
    if (i < NC2) g_ccnt[i] = 0;
    if (i < NSC) g_qcnt[i] = 0;
    if (i < 3)           g_bbenc[i] = 0x7fffffff;
    if (i >= 3 && i < 6) g_bbenc[i] = 0x80000000;
}

__global__ void k_bbox(const float* __restrict__ y, int M) {
    int i = blockIdx.x * blockDim.x + threadIdx.x;
    bool v = i < M;
    float mn[3], mx[3];
    const float INF = __int_as_float(0x7f800000);
#pragma unroll
    for (int a = 0; a < 3; ++a) {
        float p = v ? y[3 * i + a] : 0.f;
        mn[a] = v ? p : INF;
        mx[a] = v ? p : -INF;
    }
#pragma unroll
    for (int o = 16; o; o >>= 1) {
#pragma unroll
        for (int a = 0; a < 3; ++a) {
            mn[a] = fminf(mn[a], __shfl_down_sync(0xffffffffu, mn[a], o));
            mx[a] = fmaxf(mx[a], __shfl_down_sync(0xffffffffu, mx[a], o));
        }
    }
    if ((threadIdx.x & 31) == 0) {
#pragma unroll
        for (int a = 0; a < 3; ++a) {
            atomicMin(&g_bbenc[a],     fenc(mn[a]));
            atomicMax(&g_bbenc[3 + a], fenc(mx[a]));
        }
    }
}

__global__ void k_params() {
    float h[3];
#pragma unroll
    for (int a = 0; a < 3; ++a) {
        float mn = fdec(g_bbenc[a]);
        float mx = fdec(g_bbenc[3 + a]);
        float ext = fmaxf(mx - mn, 1e-6f);
        g_org[a]  = mn;
        h[a]      = ext / GS2;
        g_h[a]    = h[a];
        g_hinv[a] = GS2 / ext;
    }
    g_hmin = fminf(h[0], fminf(h[1], h[2]));

    // static offset list: all of [-2..2]^3, ordered by tier = sum(max(0,|o|-1)^2)
    int n = 0;
    for (int tier = 0; tier <= 3; ++tier) {
        for (int oz = -2; oz <= 2; ++oz)
            for (int oy = -2; oy <= 2; ++oy)
                for (int ox = -2; ox <= 2; ++ox) {
                    int mx = max(0, abs(ox) - 1);
                    int my = max(0, abs(oy) - 1);
                    int mz = max(0, abs(oz) - 1);
                    int s = mx * mx + my * my + mz * mz;
                    if (s != tier) continue;
                    g_offpack[n] = (ox + 2) | ((oy + 2) << 4) | ((oz + 2) << 8);
                    g_lbmono[n] = mx * h[0] * (mx * h[0])
                                + my * h[1] * (my * h[1])
                                + mz * h[2] * (mz * h[2]);
                    ++n;
                }
    }
    // suffix min (tier order is monotone in cell units; this makes it exact)
    float m = __int_as_float(0x7f800000);
    for (int i = LBN - 1; i >= 0; --i) {
        m = fminf(m, g_lbmono[i]);
        g_lbmono[i] = m;
    }
}

__device__ __forceinline__ int cell_of(float p, int a) {
    int c = (int)((p - g_org[a]) * g_hinv[a]);
    return min(GS2 - 1, max(0, c));
}

__global__ void k_count_atoms(const float* __restrict__ y, int M) {
    int i = blockIdx.x * blockDim.x + threadIdx.x;
    if (i >= M) return;
    int c = (cell_of(y[3 * i + 2], 2) * GS2 + cell_of(y[3 * i + 1], 1)) * GS2
          + cell_of(y[3 * i], 0);
    atomicAdd(&g_ccnt[c], 1);
}

__global__ void k_scan() {   // single block, 1024 threads, 8 cells each
    __shared__ int sp[1024];
    const int tid = threadIdx.x;
    const int base = tid * 8;
    int v[8];
    int s = 0;
#pragma unroll
    for (int j = 0; j < 8; ++j) {
        int c = base + j;
        v[j] = (c < NC2) ? g_ccnt[c] : 0;
        s += v[j];
    }
    sp[tid] = s;
    __syncthreads();
    for (int off = 1; off < 1024; off <<= 1) {
        int t = (tid >= off) ? sp[tid - off] : 0;
        __syncthreads();
        sp[tid] += t;
        __syncthreads();
    }
    int excl = sp[tid] - s;
#pragma unroll
    for (int j = 0; j < 8; ++j) {
        int c = base + j;
        if (c < NC2) { g_cstart[c] = excl; g_ccur[c] = excl; excl += v[j]; }
    }
    if (tid == 1023) g_cstart[NC2] = sp[1023];
}

__global__ void k_fill_atoms(const float* __restrict__ y, int M) {
    int i = blockIdx.x * blockDim.x + threadIdx.x;
    if (i >= M) return;
    float ax = y[3 * i], ay = y[3 * i + 1], az = y[3 * i + 2];
    int c = (cell_of(az, 2) * GS2 + cell_of(ay, 1)) * GS2 + cell_of(ax, 0);
    int slot = atomicAdd(&g_ccur[c], 1);
    g_catoms[slot] = make_float4(ax, ay, az, __int_as_float(i));
}

__global__ void k_bin_queries(const float* __restrict__ x, int N) {
    int i = blockIdx.x * blockDim.x + threadIdx.x;
    if (i >= N) return;
    int fx = cell_of(x[3 * i], 0);
    int fy = cell_of(x[3 * i + 1], 1);
    int fz = cell_of(x[3 * i + 2], 2);
    int sc = ((fz >> 1) * SC + (fy >> 1)) * SC + (fx >> 1);
    int slot = atomicAdd(&g_qcnt[sc], 1);
    if (slot < QCAP) g_qidx[sc * QCAP + slot] = i;
}

// ---- kNN: one block per supercell; staged CSR neighborhood; ordered pruned scan ----
__global__ __launch_bounds__(KB)
void k_knn(const float* __restrict__ x)
{
    __shared__ float4 satoms[RCAP];
    __shared__ int   soff[217];
    __shared__ int   sgs[216];
    __shared__ int   scnt[216];
    __shared__ float slb[LBN];
    __shared__ int   sop[LBN];

    const int tid = threadIdx.x;
    const int sc  = blockIdx.x;
    const int Sx = sc % SC, Sy = (sc / SC) % SC, Sz = sc / (SC * SC);
    const int fx0 = 2 * Sx - 2, fy0 = 2 * Sy - 2, fz0 = 2 * Sz - 2;

    for (int i = tid; i < LBN; i += KB) { slb[i] = g_lbmono[i]; sop[i] = g_offpack[i]; }

    for (int i = tid; i < 216; i += KB) {
        int lx = i % 6, ly = (i / 6) % 6, lz = i / 36;
        int gx = fx0 + lx, gy = fy0 + ly, gz = fz0 + lz;
        bool ok = (gx >= 0) & (gx < GS2) & (gy >= 0) & (gy < GS2) &
                  (gz >= 0) & (gz < GS2);
        int c  = ok ? ((gz * GS2 + gy) * GS2 + gx) : 0;
        int st = ok ? g_cstart[c] : 0;
        int cn = ok ? (g_cstart[c + 1] - st) : 0;
        sgs[i]  = st;
        scnt[i] = cn;
    }
    __syncthreads();

    if (tid < 32) {   // warp-0 exclusive scan of 216 counts (7 per lane)
        const int base = tid * 7;
        int v[7];
        int s = 0;
#pragma unroll
        for (int j = 0; j < 7; ++j) {
            int k = base + j;
            v[j] = (k < 216) ? scnt[k] : 0;
            s += v[j];
        }
        int pre = s;
#pragma unroll
        for (int o = 1; o < 32; o <<= 1) {
            int t = __shfl_up_sync(0xffffffffu, pre, o);
            if (tid >= o) pre += t;
        }
        pre -= s;   // exclusive
#pragma unroll
        for (int j = 0; j < 7; ++j) {
            int k = base + j;
            if (k < 216) soff[k] = pre;
            pre += v[j];
        }
        if (tid == 31) soff[216] = pre;
    }
    __syncthreads();

    const bool use_smem = soff[216] <= RCAP;
    if (use_smem) {
        for (int i = tid; i < 216; i += KB) {
            const int cn = scnt[i], o = soff[i], st = sgs[i];
            for (int j = 0; j < cn; ++j)
                satoms[o + j] = g_catoms[st + j];
        }
    }
    __syncthreads();

    const float ox_ = g_org[0], oy_ = g_org[1], oz_ = g_org[2];
    const float hx = g_h[0], hy = g_h[1], hz = g_h[2];
    const float hmin = g_hmin;

    const int nq = min(g_qcnt[sc], QCAP);
    const float INF = __int_as_float(0x7f800000);

    for (int t0 = 0; t0 < nq; t0 += KB) {
        const int  t      = t0 + tid;
        const bool active = t < nq;
        const int  qi     = active ? g_qidx[sc * QCAP + t] : 0;
        const float px = x[3 * qi], py = x[3 * qi + 1], pz = x[3 * qi + 2];

        const int hfx = cell_of(px, 0), hfy = cell_of(py, 1), hfz = cell_of(pz, 2);
        const int lhx = hfx - fx0, lhy = hfy - fy0, lhz = hfz - fz0;   // in {2,3}

        float dist[KNN];
        int   idx[KNN];
#pragma unroll
        for (int j = 0; j < KNN; ++j) { dist[j] = INF; idx[j] = 0; }
        float worst = active ? INF : 0.f;

        auto insert = [&](float d, int gi) {
            dist[KNN - 1] = d;
            idx[KNN - 1]  = gi;
#pragma unroll
            for (int j = KNN - 1; j > 0; --j) {
                if (dist[j] < dist[j - 1]) {
                    float td = dist[j]; dist[j] = dist[j - 1]; dist[j - 1] = td;
                    int   ti = idx[j];  idx[j]  = idx[j - 1];  idx[j - 1]  = ti;
                }
            }
            worst = dist[KNN - 1];
        };

        auto scan_smem = [&](int base, int cn) {
#pragma unroll 1
            for (int j = 0; j < cn; ++j) {
                float4 q = satoms[base + j];
                float dx = px - q.x, dy = py - q.y, dz = pz - q.z;
                float d = fmaf(dx, dx, fmaf(dy, dy, dz * dz));
                if (d < worst) insert(d, __float_as_int(q.w));
            }
        };
        auto scan_gmem = [&](int base, int cn) {
#pragma unroll 1
            for (int j = 0; j < cn; ++j) {
                float4 q = g_catoms[base + j];
                float dx = px - q.x, dy = py - q.y, dz = pz - q.z;
                float d = fmaf(dx, dx, fmaf(dy, dy, dz * dz));
                if (d < worst) insert(d, __float_as_int(q.w));
            }
        };

        // ---- ordered neighborhood scan with warp-uniform early break ----
#pragma unroll 1
        for (int i = 0; i < LBN; ++i) {
            if (__all_sync(0xffffffffu, worst <= slb[i])) break;
            const int op = sop[i];
            const int cx = lhx + (op & 15) - 2;
            const int cy = lhy + ((op >> 4) & 15) - 2;
            const int cz = lhz + ((op >> 8) & 15) - 2;
            const int lc = (cz * 6 + cy) * 6 + cx;
            const int cn = scnt[lc];
            if (cn == 0) continue;
            // exact minDist to this fine cell's box
            const int gx = fx0 + cx, gy = fy0 + cy, gz = fz0 + cz;
            const float lox = ox_ + gx * hx, loy = oy_ + gy * hy, loz = oz_ + gz * hz;
            float tx = fmaxf(fmaxf(lox - px, px - (lox + hx)), 0.f);
            float ty = fmaxf(fmaxf(loy - py, py - (loy + hy)), 0.f);
            float tz = fmaxf(fmaxf(loz - pz, pz - (loz + hz)), 0.f);
            float mind = fmaf(tx, tx, fmaf(ty, ty, tz * tz));
            if (mind < worst) {
                if (use_smem) scan_smem(soff[lc], cn);
                else          scan_gmem(sgs[lc], cn);
            }
        }

        // ---- rare fallback: Chebyshev rings R>=3 over global CSR ----
        {
            float covg = 2.f * hmin - 1e-4f;
            covg *= covg;                 // unscanned cells have minDist^2 >= covg
            int R = 3;
#pragma unroll 1
            while (R < GS2) {
                float rl = (R - 1) * hmin - 1e-4f;
                rl = rl * rl;
                bool need = active && (worst > covg) && (worst > rl);
                if (!__any_sync(0xffffffffu, need)) break;
                if (need) {
                    const int zlo = max(hfz - R, 0), zhi = min(hfz + R, GS2 - 1);
                    const int ylo = max(hfy - R, 0), yhi = min(hfy + R, GS2 - 1);
                    const int xlo = max(hfx - R, 0), xhi = min(hfx + R, GS2 - 1);
                    for (int cz = zlo; cz <= zhi; ++cz)
                        for (int cy = ylo; cy <= yhi; ++cy)
                            for (int cx = xlo; cx <= xhi; ++cx) {
                                int ch = max(abs(cx - hfx),
                                         max(abs(cy - hfy), abs(cz - hfz)));
                                if (ch != R) continue;
                                int c = (cz * GS2 + cy) * GS2 + cx;
                                int st = g_cstart[c];
                                int cn = g_cstart[c + 1] - st;
                                if (cn == 0) continue;
                                float lox = ox_ + cx * hx, loy = oy_ + cy * hy,
                                      loz = oz_ + cz * hz;
                                float tx = fmaxf(fmaxf(lox - px, px - (lox + hx)), 0.f);
                                float ty = fmaxf(fmaxf(loy - py, py - (loy + hy)), 0.f);
                                float tz = fmaxf(fmaxf(loz - pz, pz - (loz + hz)), 0.f);
                                float mind = fmaf(tx, tx, fmaf(ty, ty, tz * tz));
                                if (mind < worst) scan_gmem(st, cn);
                            }
                }
                ++R;
            }
        }

        if (active) {
            float4* dp = reinterpret_cast<float4*>(g_ndist + (size_t)qi * KNN);
            int4*   ip = reinterpret_cast<int4*>(g_nidx + (size_t)qi * KNN);
            dp[0] = make_float4(dist[0],  dist[1],  dist[2],  dist[3]);
            dp[1] = make_float4(dist[4],  dist[5],  dist[6],  dist[7]);
            dp[2] = make_float4(dist[8],  dist[9],  dist[10], dist[11]);
            dp[3] = make_float4(dist[12], dist[13], dist[14], dist[15]);
            ip[0] = make_int4(idx[0],  idx[1],  idx[2],  idx[3]);
            ip[1] = make_int4(idx[4],  idx[5],  idx[6],  idx[7]);
            ip[2] = make_int4(idx[8],  idx[9],  idx[10], idx[11]);
            ip[3] = make_int4(idx[12], idx[13], idx[14], idx[15]);
        }
    }
}

// ---- MLP over the K neighbors ----
__global__ __launch_bounds__(128)
void k_mlp(const float* __restrict__ atype,
           const float* __restrict__ W1, const float* __restrict__ b1,
           const float* __restrict__ W2, const float* __restrict__ b2,
           const float* __restrict__ W3, const float* __restrict__ b3,
           const float* __restrict__ bn1g, const float* __restrict__ bn1b,
           const float* __restrict__ bn1m, const float* __restrict__ bn1v,
           const float* __restrict__ bn2g, const float* __restrict__ bn2b,
           const float* __restrict__ bn2m, const float* __restrict__ bn2v,
           float* __restrict__ out, int N)
{
    __shared__ float sW1[(D + 1) * D];
    __shared__ float sW2[D * D];
    __shared__ float sW3[2 * D * D];
    __shared__ float sb1[D], sb2[D], sb3[D];
    __shared__ float ss1[D], st1[D], ss2[D], st2[D];

    const int tid = threadIdx.x;
    for (int i = tid; i < (D + 1) * D; i += 128) sW1[i] = W1[i];
    for (int i = tid; i < D * D;       i += 128) sW2[i] = W2[i];
    for (int i = tid; i < 2 * D * D;   i += 128) sW3[i] = W3[i];
    if (tid < D) {
        sb1[tid] = b1[tid];
        sb2[tid] = b2[tid];
        sb3[tid] = b3[tid];
        float s1 = bn1g[tid] * rsqrtf(bn1v[tid] + 1e-5f);
        ss1[tid] = s1;
        st1[tid] = fmaf(-bn1m[tid], s1, bn1b[tid]);
        float s2 = bn2g[tid] * rsqrtf(bn2v[tid] + 1e-5f);
        ss2[tid] = s2;
        st2[tid] = fmaf(-bn2m[tid], s2, bn2b[tid]);
    }
    __syncthreads();

    const int n = blockIdx.x * 128 + tid;
    if (n >= N) return;

    const float4* dp = reinterpret_cast<const float4*>(g_ndist + (size_t)n * KNN);
    const int4*   ip = reinterpret_cast<const int4*>(g_nidx + (size_t)n * KNN);
    float4 dv[4] = {dp[0], dp[1], dp[2], dp[3]};
    int4   iv[4] = {ip[0], ip[1], ip[2], ip[3]};
    const float* dists = reinterpret_cast<const float*>(dv);
    const int*   idxs  = reinterpret_cast<const int*>(iv);

    float fx1[D], fx2[D];
#pragma unroll
    for (int d = 0; d < D; ++d) { fx1[d] = 0.f; fx2[d] = 0.f; }

#pragma unroll 1
    for (int k = 0; k < KNN; ++k) {
        const int   j  = idxs[k];
        const float dk = dists[k];

        const float4* ap = reinterpret_cast<const float4*>(atype + (size_t)j * D);
        float4 a0 = ap[0], a1 = ap[1], a2 = ap[2], a3 = ap[3];
        float f[D + 1] = {a0.x, a0.y, a0.z, a0.w,
                          a1.x, a1.y, a1.z, a1.w,
                          a2.x, a2.y, a2.z, a2.w,
                          a3.x, a3.y, a3.z, a3.w,
                          1.0f / dk};

        float h[D];
#pragma unroll
        for (int d = 0; d < D; ++d) h[d] = sb1[d];
#pragma unroll
        for (int s = 0; s < D + 1; ++s) {
            const float ft = f[s];
#pragma unroll
            for (int d = 0; d < D; ++d) h[d] = fmaf(ft, sW1[s * D + d], h[d]);
        }
#pragma unroll
        for (int d = 0; d < D; ++d) {
            float v = h[d];
            v = (v > 0.f) ? v : 0.2f * v;
            v = fmaf(v, ss1[d], st1[d]);
            h[d] = v;
            fx1[d] += v;
        }

        float h2[D];
#pragma unroll
        for (int d = 0; d < D; ++d) h2[d] = sb2[d];
#pragma unroll
        for (int s = 0; s < D; ++s) {
            const float ht = h[s];
#pragma unroll
            for (int d = 0; d < D; ++d) h2[d] = fmaf(ht, sW2[s * D + d], h2[d]);
        }
#pragma unroll
        for (int d = 0; d < D; ++d) {
            float v = h2[d];
            v = (v > 0.f) ? v : 0.2f * v;
            fx2[d] += fmaf(v, ss2[d], st2[d]);
        }
    }

    float o[D];
#pragma unroll
    for (int d = 0; d < D; ++d) o[d] = sb3[d];
#pragma unroll
    for (int s = 0; s < D; ++s) {
        const float a = fx1[s];
#pragma unroll
        for (int d = 0; d < D; ++d) o[d] = fmaf(a, sW3[s * D + d], o[d]);
    }
#pragma unroll
    for (int s = 0; s < D; ++s) {
        const float a = fx2[s];
#pragma unroll
        for (int d = 0; d < D; ++d) o[d] = fmaf(a, sW3[(D + s) * D + d], o[d]);
    }

    float4* op = reinterpret_cast<float4*>(out + (size_t)n * D);
    op[0] = make_float4(o[0],  o[1],  o[2],  o[3]);
    op[1] = make_float4(o[4],  o[5],  o[6],  o[7]);
    op[2] = make_float4(o[8],  o[9],  o[10], o[11]);
    op[3] = make_float4(o[12], o[13], o[14], o[15]);
}

} // namespace

extern "C" void kernel_launch(void* const* d_in, const int* in_sizes, int n_in,
                              void* d_out, int out_size)
{
    const float* x     = (const float*)d_in[0];
    const float* y     = (const float*)d_in[1];
    const float* atype = (const float*)d_in[2];
    const float* W1    = (const float*)d_in[5];
    const float* b1    = (const float*)d_in[6];
    const float* W2    = (const float*)d_in[7];
    const float* b2    = (const float*)d_in[8];
    const float* W3    = (const float*)d_in[9];
    const float* b3    = (const float*)d_in[10];
    const float* bn1g  = (const float*)d_in[11];
    const float* bn1b  = (const float*)d_in[12];
    const float* bn1m  = (const float*)d_in[13];
    const float* bn1v  = (const float*)d_in[14];
    const float* bn2g  = (const float*)d_in[15];
    const float* bn2b  = (const float*)d_in[16];
    const float* bn2m  = (const float*)d_in[17];
    const float* bn2v  = (const float*)d_in[18];

    const int N = in_sizes[0] / 3;
    const int M = in_sizes[1] / 3;

    k_init<<<(NC2 + 255) / 256, 256>>>();
    k_bbox<<<(M + 255) / 256, 256>>>(y, M);
    k_params<<<1, 1>>>();
    k_count_atoms<<<(M + 255) / 256, 256>>>(y, M);
    k_scan<<<1, 1024>>>();
    k_fill_atoms<<<(M + 255) / 256, 256>>>(y, M);
    k_bin_queries<<<(N + 255) / 256, 256>>>(x, N);
    k_knn<<<NSC, KB>>>(x);
    k_mlp<<<(N + 127) / 128, 128>>>(atype,
                                    W1, b1, W2, b2, W3, b3,
                                    bn1g, bn1b, bn1m, bn1v,
                                    bn2g, bn2b, bn2m, bn2v,
                                    (float*)d_out, N);
}